// round 2
// baseline (speedup 1.0000x reference)
#include <cuda_runtime.h>
#include <cstdint>

#define NB   2
#define NPTS 8192
#define CIN  128
#define COUT 128
#define KNN  21

// flipped-encoding of FLT_MAX with max index: larger than any real key,
// decodes to tau = FLT_MAX (never NaN)
#define SENT 0xFF7FFFFFFFFFFFFFull

// ---------------- scratch (device globals; no allocation allowed) -------------
__device__ __align__(16) float g_Ageo [NB * NPTS * 128];
__device__ __align__(16) float g_Btgeo[NB * NPTS * 128];
__device__ __align__(16) float g_Afeat[NB * NPTS * 128];
__device__ __align__(16) float g_Btfeat[NB * NPTS * 128];
__device__ int   g_idx[NB * NPTS * KNN];
__device__ __align__(16) float g_scale[256];
__device__ __align__(16) float g_shift[256];

// ---------------- BN constants ----------------
__global__ void constants_kernel(const float* __restrict__ gg, const float* __restrict__ bg,
                                 const float* __restrict__ mg, const float* __restrict__ vg,
                                 const float* __restrict__ gf, const float* __restrict__ bf,
                                 const float* __restrict__ mf, const float* __restrict__ vf) {
    int c = threadIdx.x;
    if (c < 128) {
        float inv = gg[c] * rsqrtf(vg[c] + 1e-5f);
        g_scale[c] = inv;
        g_shift[c] = bg[c] - mg[c] * inv;
    } else {
        int o = c - 128;
        float inv = gf[o] * rsqrtf(vf[o] + 1e-5f);
        g_scale[c] = inv;
        g_shift[c] = bf[o] - mf[o] * inv;
    }
}

// ---------------- geo precompute --------------------------------------------
__global__ void geo_precompute_kernel(const float* __restrict__ xyz,
                                      const float* __restrict__ W_geo) {
    int g = blockIdx.x * blockDim.x + threadIdx.x;
    int o = g & 127;
    int r = g >> 7;
    int n = r & (NPTS - 1);
    int b = r >> 13;
    const float* p = xyz + ((size_t)b * NPTS + n) * 3;
    float x = p[0], y = p[1], z = p[2];
    float w0 = W_geo[o * 6 + 0], w1 = W_geo[o * 6 + 1], w2 = W_geo[o * 6 + 2];
    float w3 = W_geo[o * 6 + 3], w4 = W_geo[o * 6 + 4], w5 = W_geo[o * 6 + 5];
    size_t base = ((size_t)b * NPTS + n) * 128 + o;
    g_Ageo [base] = fmaf(w0 - w3, x, fmaf(w1 - w4, y, (w2 - w5) * z));
    g_Btgeo[base] = fmaf(w3, x, fmaf(w4, y, w5 * z));
}

// ---------------- feat precompute GEMMs -------------------------------------
__global__ void __launch_bounds__(128) feat_gemm_kernel(const float* __restrict__ f,
                                                        const float* __restrict__ W_feat) {
    __shared__ float sf[128][32];
    int b  = blockIdx.y;
    int n0 = blockIdx.x * 32;

    for (int t = threadIdx.x; t < 128 * 32; t += 128) {
        int c = t >> 5, n = t & 31;
        sf[c][n] = f[((size_t)b * 128 + c) * NPTS + n0 + n];
    }
    __syncthreads();

    int o = threadIdx.x;
    float accA[32], accB[32];
#pragma unroll
    for (int n = 0; n < 32; ++n) { accA[n] = 0.f; accB[n] = 0.f; }

    for (int c = 0; c < 128; ++c) {
        float w1 = __ldg(&W_feat[o * 256 + c]);
        float w2 = __ldg(&W_feat[o * 256 + 128 + c]);
        float wm = w1 - w2;
#pragma unroll
        for (int n = 0; n < 32; ++n) {
            float fv = sf[c][n];
            accA[n] = fmaf(wm, fv, accA[n]);
            accB[n] = fmaf(w2, fv, accB[n]);
        }
    }
#pragma unroll
    for (int n = 0; n < 32; ++n) {
        size_t base = ((size_t)b * NPTS + n0 + n) * 128 + o;
        g_Afeat [base] = accA[n];
        g_Btfeat[base] = accB[n];
    }
}

// ---------------- KNN: WarpSelect (warp-wide threshold + lane buffers) -------
#define KNN_CHUNK 1024
__global__ void __launch_bounds__(256) knn_kernel(const float* __restrict__ xyz) {
    __shared__ float4 sc[KNN_CHUNK];
    int b    = blockIdx.y;
    int warp = threadIdx.x >> 5;
    int lane = threadIdx.x & 31;
    int q    = blockIdx.x * 8 + warp;

    const float* base = xyz + (size_t)b * NPTS * 3;
    float qx = base[q * 3 + 0];
    float qy = base[q * 3 + 1];
    float qz = base[q * 3 + 2];
    float qd2 = fmaf(qx, qx, fmaf(qy, qy, qz * qz));

    unsigned long long list[KNN];
#pragma unroll
    for (int i = 0; i < KNN; ++i) list[i] = SENT;

    unsigned long long buf0 = 0, buf1 = 0, buf2 = 0, buf3 = 0;
    int cnt = 0;
    float tau = __int_as_float(0x7f7fffff);   // FLT_MAX: everything passes

    for (int c0 = 0; c0 < NPTS; c0 += KNN_CHUNK) {
        __syncthreads();
        for (int i = threadIdx.x; i < KNN_CHUNK; i += 256) {
            int j = c0 + i;
            float x = base[j * 3 + 0];
            float y = base[j * 3 + 1];
            float z = base[j * 3 + 2];
            float d2 = fmaf(x, x, fmaf(y, y, z * z));
            sc[i] = make_float4(x, y, z, d2);
        }
        __syncthreads();

#pragma unroll 4
        for (int i = lane; i < KNN_CHUNK; i += 32) {
            float4 c = sc[i];
            float dot  = fmaf(qx, c.x, fmaf(qy, c.y, qz * c.z));
            float dist = fmaf(-2.f, dot, qd2 + c.w);   // same formula as reference
            // fast filter: can this candidate possibly be in the global top-21?
            if (dist <= tau) {
                unsigned u = __float_as_uint(dist);
                u ^= ((unsigned)((int)u >> 31)) | 0x80000000u;   // order-preserving flip
                unsigned long long key =
                    ((unsigned long long)u << 32) | (unsigned)(c0 + i);
                if      (cnt == 0) buf0 = key;
                else if (cnt == 1) buf1 = key;
                else if (cnt == 2) buf2 = key;
                else               buf3 = key;
                ++cnt;
            }
            // flush when any lane's buffer is full (warp-uniform slow path)
            if (__any_sync(0xffffffffu, cnt >= 4)) {
#pragma unroll
                for (int t = 0; t < 4; ++t) {
                    unsigned long long cur =
                        (t == 0) ? buf0 : (t == 1) ? buf1 : (t == 2) ? buf2 : buf3;
                    if (t < cnt && cur < list[KNN - 1]) {
#pragma unroll
                        for (int s = 0; s < KNN; ++s) {
                            unsigned long long m = list[s];
                            bool lt = cur < m;
                            list[s] = lt ? cur : m;
                            cur     = lt ? m : cur;
                        }
                    }
                }
                cnt = 0;
                // tau = warp-min of per-lane 21st-best (valid global bound)
                unsigned long long t20 = list[KNN - 1];
#pragma unroll
                for (int off = 16; off; off >>= 1) {
                    unsigned long long o = __shfl_xor_sync(0xffffffffu, t20, off);
                    t20 = (o < t20) ? o : t20;
                }
                unsigned th = (unsigned)(t20 >> 32);
                th ^= (~((unsigned)((int)th >> 31))) | 0x80000000u;   // unflip
                tau = __uint_as_float(th);
            }
        }
    }

    // flush remaining buffered candidates
    if (__any_sync(0xffffffffu, cnt > 0)) {
#pragma unroll
        for (int t = 0; t < 4; ++t) {
            unsigned long long cur =
                (t == 0) ? buf0 : (t == 1) ? buf1 : (t == 2) ? buf2 : buf3;
            if (t < cnt && cur < list[KNN - 1]) {
#pragma unroll
                for (int s = 0; s < KNN; ++s) {
                    unsigned long long m = list[s];
                    bool lt = cur < m;
                    list[s] = lt ? cur : m;
                    cur     = lt ? m : cur;
                }
            }
        }
    }

    // merge 32 sorted per-lane lists -> global top-21
    unsigned long long head = list[0];
    unsigned long long mine = 0;
    for (int r = 0; r < KNN; ++r) {
        unsigned long long v = head;
        int src = lane;
#pragma unroll
        for (int off = 16; off; off >>= 1) {
            unsigned long long ov = __shfl_xor_sync(0xffffffffu, v, off);
            int os = __shfl_xor_sync(0xffffffffu, src, off);
            if (ov < v) { v = ov; src = os; }
        }
        if (lane == r) mine = v;
        if (lane == src) {
#pragma unroll
            for (int s = 0; s < KNN - 1; ++s) list[s] = list[s + 1];
            list[KNN - 1] = SENT;
            head = list[0];
        }
    }
    if (lane < KNN)
        g_idx[((size_t)b * NPTS + q) * KNN + lane] = (int)(mine & 0xffffffffu);
}

// ---------------- gather-max + epilogue --------------------------------------
__device__ __forceinline__ float4 fmax4(float4 a, float4 b) {
    return make_float4(fmaxf(a.x, b.x), fmaxf(a.y, b.y),
                       fmaxf(a.z, b.z), fmaxf(a.w, b.w));
}

__global__ void __launch_bounds__(256) gather_max_kernel(float* __restrict__ out) {
    __shared__ int   sidx[32][KNN];
    __shared__ float sout[256 * 33];

    int b    = blockIdx.y;
    int n0   = blockIdx.x * 32;
    int warp = threadIdx.x >> 5;
    int lane = threadIdx.x & 31;

    for (int t = threadIdx.x; t < 32 * KNN; t += 256)
        sidx[t / KNN][t % KNN] = g_idx[((size_t)b * NPTS + n0) * KNN + t];
    __syncthreads();

    const float4* BG = (const float4*)g_Btgeo;
    const float4* BF = (const float4*)g_Btfeat;
    const float4* AG = (const float4*)g_Ageo;
    const float4* AF = (const float4*)g_Afeat;
    const float4* S4 = (const float4*)g_scale;
    const float4* H4 = (const float4*)g_shift;

    float4 scg = S4[lane],        shg = H4[lane];
    float4 scf = S4[32 + lane],   shf = H4[32 + lane];

    for (int pi = 0; pi < 4; ++pi) {
        int p = warp * 4 + pi;
        int n = n0 + p;
        float4 mg = make_float4(-3.4e38f, -3.4e38f, -3.4e38f, -3.4e38f);
        float4 mf = mg;
#pragma unroll
        for (int k = 0; k < KNN; ++k) {
            int j = sidx[p][k];
            size_t col = ((size_t)b * NPTS + j) * 32 + lane;
            mg = fmax4(mg, BG[col]);
            mf = fmax4(mf, BF[col]);
        }
        size_t acol = ((size_t)b * NPTS + n) * 32 + lane;
        float4 ag = AG[acol];
        float4 af = AF[acol];

        int cg = lane * 4;
        sout[(cg + 0) * 33 + p] = fmaxf(fmaf(mg.x + ag.x, scg.x, shg.x), 0.f);
        sout[(cg + 1) * 33 + p] = fmaxf(fmaf(mg.y + ag.y, scg.y, shg.y), 0.f);
        sout[(cg + 2) * 33 + p] = fmaxf(fmaf(mg.z + ag.z, scg.z, shg.z), 0.f);
        sout[(cg + 3) * 33 + p] = fmaxf(fmaf(mg.w + ag.w, scg.w, shg.w), 0.f);
        int cf = 128 + lane * 4;
        sout[(cf + 0) * 33 + p] = fmaxf(fmaf(mf.x + af.x, scf.x, shf.x), 0.f);
        sout[(cf + 1) * 33 + p] = fmaxf(fmaf(mf.y + af.y, scf.y, shf.y), 0.f);
        sout[(cf + 2) * 33 + p] = fmaxf(fmaf(mf.z + af.z, scf.z, shf.z), 0.f);
        sout[(cf + 3) * 33 + p] = fmaxf(fmaf(mf.w + af.w, scf.w, shf.w), 0.f);
    }
    __syncthreads();

    for (int c = warp; c < 256; c += 8)
        out[((size_t)b * 256 + c) * NPTS + n0 + lane] = sout[c * 33 + lane];
}

// ---------------- launch ------------------------------------------------------
extern "C" void kernel_launch(void* const* d_in, const int* in_sizes, int n_in,
                              void* d_out, int out_size) {
    const float* xyz    = (const float*)d_in[0];
    const float* f      = (const float*)d_in[1];
    const float* W_geo  = (const float*)d_in[2];
    const float* g_geo  = (const float*)d_in[3];
    const float* b_geo  = (const float*)d_in[4];
    const float* m_geo  = (const float*)d_in[5];
    const float* v_geo  = (const float*)d_in[6];
    const float* W_feat = (const float*)d_in[7];
    const float* g_feat = (const float*)d_in[8];
    const float* b_feat = (const float*)d_in[9];
    const float* m_feat = (const float*)d_in[10];
    const float* v_feat = (const float*)d_in[11];
    float* out = (float*)d_out;

    constants_kernel<<<1, 256>>>(g_geo, b_geo, m_geo, v_geo,
                                 g_feat, b_feat, m_feat, v_feat);
    geo_precompute_kernel<<<(NB * NPTS * 128) / 256, 256>>>(xyz, W_geo);
    feat_gemm_kernel<<<dim3(NPTS / 32, NB), 128>>>(f, W_feat);
    knn_kernel<<<dim3(NPTS / 8, NB), 256>>>(xyz);
    gather_max_kernel<<<dim3(NPTS / 32, NB), 256>>>(out);
}

// round 3
// speedup vs baseline: 3.9590x; 3.9590x over previous
#include <cuda_runtime.h>
#include <cstdint>

#define NB   2
#define NPTS 8192
#define CIN  128
#define COUT 128
#define KNN  21
#define FULLM 0xffffffffu
#define SENT 0xFFFFFFFFFFFFFFFFull
#define FINF __int_as_float(0x7f800000)

// ---------------- scratch (device globals; no allocation allowed) -------------
__device__ __align__(16) float g_Ageo [NB * NPTS * 128];
__device__ __align__(16) float g_Btgeo[NB * NPTS * 128];
__device__ __align__(16) float g_Afeat[NB * NPTS * 128];
__device__ __align__(16) float g_Btfeat[NB * NPTS * 128];
__device__ int   g_idx[NB * NPTS * KNN];
__device__ __align__(16) float g_scale[256];
__device__ __align__(16) float g_shift[256];

// ---------------- BN constants ----------------
__global__ void constants_kernel(const float* __restrict__ gg, const float* __restrict__ bg,
                                 const float* __restrict__ mg, const float* __restrict__ vg,
                                 const float* __restrict__ gf, const float* __restrict__ bf,
                                 const float* __restrict__ mf, const float* __restrict__ vf) {
    int c = threadIdx.x;
    if (c < 128) {
        float inv = gg[c] * rsqrtf(vg[c] + 1e-5f);
        g_scale[c] = inv;
        g_shift[c] = bg[c] - mg[c] * inv;
    } else {
        int o = c - 128;
        float inv = gf[o] * rsqrtf(vf[o] + 1e-5f);
        g_scale[c] = inv;
        g_shift[c] = bf[o] - mf[o] * inv;
    }
}

// ---------------- geo precompute --------------------------------------------
__global__ void geo_precompute_kernel(const float* __restrict__ xyz,
                                      const float* __restrict__ W_geo) {
    int g = blockIdx.x * blockDim.x + threadIdx.x;
    int o = g & 127;
    int r = g >> 7;
    int n = r & (NPTS - 1);
    int b = r >> 13;
    const float* p = xyz + ((size_t)b * NPTS + n) * 3;
    float x = p[0], y = p[1], z = p[2];
    float w0 = W_geo[o * 6 + 0], w1 = W_geo[o * 6 + 1], w2 = W_geo[o * 6 + 2];
    float w3 = W_geo[o * 6 + 3], w4 = W_geo[o * 6 + 4], w5 = W_geo[o * 6 + 5];
    size_t base = ((size_t)b * NPTS + n) * 128 + o;
    g_Ageo [base] = fmaf(w0 - w3, x, fmaf(w1 - w4, y, (w2 - w5) * z));
    g_Btgeo[base] = fmaf(w3, x, fmaf(w4, y, w5 * z));
}

// ---------------- feat precompute GEMMs -------------------------------------
__global__ void __launch_bounds__(128) feat_gemm_kernel(const float* __restrict__ f,
                                                        const float* __restrict__ W_feat) {
    __shared__ float sf[128][32];
    int b  = blockIdx.y;
    int n0 = blockIdx.x * 32;

    for (int t = threadIdx.x; t < 128 * 32; t += 128) {
        int c = t >> 5, n = t & 31;
        sf[c][n] = f[((size_t)b * 128 + c) * NPTS + n0 + n];
    }
    __syncthreads();

    int o = threadIdx.x;
    float accA[32], accB[32];
#pragma unroll
    for (int n = 0; n < 32; ++n) { accA[n] = 0.f; accB[n] = 0.f; }

    for (int c = 0; c < 128; ++c) {
        float w1 = __ldg(&W_feat[o * 256 + c]);
        float w2 = __ldg(&W_feat[o * 256 + 128 + c]);
        float wm = w1 - w2;
#pragma unroll
        for (int n = 0; n < 32; ++n) {
            float fv = sf[c][n];
            accA[n] = fmaf(wm, fv, accA[n]);
            accB[n] = fmaf(w2, fv, accB[n]);
        }
    }
#pragma unroll
    for (int n = 0; n < 32; ++n) {
        size_t base = ((size_t)b * NPTS + n0 + n) * 128 + o;
        g_Afeat [base] = accA[n];
        g_Btfeat[base] = accB[n];
    }
}

// ---------------- KNN: warp-distributed sorted top-32 + two-pass -------------
#define KNN_CHUNK 1024
#define QCAP 64
__global__ void __launch_bounds__(256) knn_kernel(const float* __restrict__ xyz) {
    __shared__ float4 sc[KNN_CHUNK];
    __shared__ unsigned long long sQ[8][QCAP];

    int b    = blockIdx.y;
    int warp = threadIdx.x >> 5;
    int lane = threadIdx.x & 31;
    int q    = blockIdx.x * 8 + warp;

    const float* base = xyz + (size_t)b * NPTS * 3;
    float qx = base[q * 3 + 0];
    float qy = base[q * 3 + 1];
    float qz = base[q * 3 + 2];
    float qd2 = fmaf(qx, qx, fmaf(qy, qy, qz * qz));

    // warp-distributed sorted list: lane l holds l-th smallest distance seen
    float elem = FINF;
    float tau  = FINF;   // = elem at lane 20 (the warp-wide 21st smallest)

    // -------- pass 1: find d21 (21st smallest distance) --------
    for (int c0 = 0; c0 < NPTS; c0 += KNN_CHUNK) {
        __syncthreads();
        for (int i = threadIdx.x; i < KNN_CHUNK; i += 256) {
            int j = c0 + i;
            float x = base[j * 3 + 0];
            float y = base[j * 3 + 1];
            float z = base[j * 3 + 2];
            float d2 = fmaf(x, x, fmaf(y, y, z * z));
            sc[i] = make_float4(x, y, z, d2);
        }
        __syncthreads();

#pragma unroll 2
        for (int i = lane; i < KNN_CHUNK; i += 32) {
            float4 c = sc[i];
            float dot  = fmaf(qx, c.x, fmaf(qy, c.y, qz * c.z));
            float dist = fmaf(-2.f, dot, qd2 + c.w);   // reference formula
            unsigned m = __ballot_sync(FULLM, dist <= tau);
            if (m) {
                do {
                    int src = __ffs(m) - 1;
                    m &= m - 1;
                    float v = __shfl_sync(FULLM, dist, src);
                    unsigned gt = __ballot_sync(FULLM, elem > v);
                    if (gt) {
                        int pos = __ffs(gt) - 1;
                        float prev = __shfl_up_sync(FULLM, elem, 1);
                        if (lane > pos)       elem = prev;
                        else if (lane == pos) elem = v;
                    }
                } while (m);
                tau = __shfl_sync(FULLM, elem, KNN - 1);
            }
        }
    }
    float d21 = tau;   // warp-uniform 21st smallest distance

    // -------- pass 2: collect (dist, idx) for all dist <= d21, in index order --------
    unsigned cnt = 0;
    for (int c0 = 0; c0 < NPTS; c0 += KNN_CHUNK) {
        __syncthreads();
        for (int i = threadIdx.x; i < KNN_CHUNK; i += 256) {
            int j = c0 + i;
            float x = base[j * 3 + 0];
            float y = base[j * 3 + 1];
            float z = base[j * 3 + 2];
            float d2 = fmaf(x, x, fmaf(y, y, z * z));
            sc[i] = make_float4(x, y, z, d2);
        }
        __syncthreads();

#pragma unroll 2
        for (int i = lane; i < KNN_CHUNK; i += 32) {
            float4 c = sc[i];
            float dot  = fmaf(qx, c.x, fmaf(qy, c.y, qz * c.z));
            float dist = fmaf(-2.f, dot, qd2 + c.w);
            bool hit = (dist <= d21);
            unsigned m = __ballot_sync(FULLM, hit);
            if (m) {
                if (hit) {
                    unsigned off = cnt + __popc(m & ((1u << lane) - 1u));
                    if (off < QCAP) {
                        unsigned u = __float_as_uint(dist);
                        u ^= ((unsigned)((int)u >> 31)) | 0x80000000u;  // order flip
                        sQ[warp][off] =
                            ((unsigned long long)u << 32) | (unsigned)(c0 + i);
                    }
                }
                cnt += __popc(m);
            }
        }
    }

    // -------- final: top-21 of collected queue by (dist, idx) --------
    int n = (cnt < QCAP) ? (int)cnt : QCAP;
    unsigned long long k0 = (lane      < n) ? sQ[warp][lane]      : SENT;
    unsigned long long k1 = (lane + 32 < n) ? sQ[warp][lane + 32] : SENT;
    int myidx = 0;
#pragma unroll 1
    for (int r = 0; r < KNN; ++r) {
        unsigned long long v = (k0 < k1) ? k0 : k1;
        unsigned long long best = v;
        int bsrc = lane;
#pragma unroll
        for (int off = 16; off; off >>= 1) {
            unsigned long long ov = __shfl_xor_sync(FULLM, best, off);
            int os = __shfl_xor_sync(FULLM, bsrc, off);
            if (ov < best || (ov == best && os < bsrc)) { best = ov; bsrc = os; }
        }
        if (lane == r) myidx = (int)(best & 0xffffffffu);
        if (lane == bsrc) {
            if (k0 < k1) k0 = SENT; else k1 = SENT;
        }
    }
    if (lane < KNN)
        g_idx[((size_t)b * NPTS + q) * KNN + lane] = myidx;
}

// ---------------- gather-max + epilogue --------------------------------------
__device__ __forceinline__ float4 fmax4(float4 a, float4 b) {
    return make_float4(fmaxf(a.x, b.x), fmaxf(a.y, b.y),
                       fmaxf(a.z, b.z), fmaxf(a.w, b.w));
}

__global__ void __launch_bounds__(256) gather_max_kernel(float* __restrict__ out) {
    __shared__ int   sidx[32][KNN];
    __shared__ float sout[256 * 33];

    int b    = blockIdx.y;
    int n0   = blockIdx.x * 32;
    int warp = threadIdx.x >> 5;
    int lane = threadIdx.x & 31;

    for (int t = threadIdx.x; t < 32 * KNN; t += 256)
        sidx[t / KNN][t % KNN] = g_idx[((size_t)b * NPTS + n0) * KNN + t];
    __syncthreads();

    const float4* BG = (const float4*)g_Btgeo;
    const float4* BF = (const float4*)g_Btfeat;
    const float4* AG = (const float4*)g_Ageo;
    const float4* AF = (const float4*)g_Afeat;
    const float4* S4 = (const float4*)g_scale;
    const float4* H4 = (const float4*)g_shift;

    float4 scg = S4[lane],        shg = H4[lane];
    float4 scf = S4[32 + lane],   shf = H4[32 + lane];

    for (int pi = 0; pi < 4; ++pi) {
        int p = warp * 4 + pi;
        int n = n0 + p;
        float4 mg = make_float4(-3.4e38f, -3.4e38f, -3.4e38f, -3.4e38f);
        float4 mf = mg;
#pragma unroll
        for (int k = 0; k < KNN; ++k) {
            int j = sidx[p][k];
            size_t col = ((size_t)b * NPTS + j) * 32 + lane;
            mg = fmax4(mg, BG[col]);
            mf = fmax4(mf, BF[col]);
        }
        size_t acol = ((size_t)b * NPTS + n) * 32 + lane;
        float4 ag = AG[acol];
        float4 af = AF[acol];

        int cg = lane * 4;
        sout[(cg + 0) * 33 + p] = fmaxf(fmaf(mg.x + ag.x, scg.x, shg.x), 0.f);
        sout[(cg + 1) * 33 + p] = fmaxf(fmaf(mg.y + ag.y, scg.y, shg.y), 0.f);
        sout[(cg + 2) * 33 + p] = fmaxf(fmaf(mg.z + ag.z, scg.z, shg.z), 0.f);
        sout[(cg + 3) * 33 + p] = fmaxf(fmaf(mg.w + ag.w, scg.w, shg.w), 0.f);
        int cf = 128 + lane * 4;
        sout[(cf + 0) * 33 + p] = fmaxf(fmaf(mf.x + af.x, scf.x, shf.x), 0.f);
        sout[(cf + 1) * 33 + p] = fmaxf(fmaf(mf.y + af.y, scf.y, shf.y), 0.f);
        sout[(cf + 2) * 33 + p] = fmaxf(fmaf(mf.z + af.z, scf.z, shf.z), 0.f);
        sout[(cf + 3) * 33 + p] = fmaxf(fmaf(mf.w + af.w, scf.w, shf.w), 0.f);
    }
    __syncthreads();

    for (int c = warp; c < 256; c += 8)
        out[((size_t)b * 256 + c) * NPTS + n0 + lane] = sout[c * 33 + lane];
}

// ---------------- launch ------------------------------------------------------
extern "C" void kernel_launch(void* const* d_in, const int* in_sizes, int n_in,
                              void* d_out, int out_size) {
    const float* xyz    = (const float*)d_in[0];
    const float* f      = (const float*)d_in[1];
    const float* W_geo  = (const float*)d_in[2];
    const float* g_geo  = (const float*)d_in[3];
    const float* b_geo  = (const float*)d_in[4];
    const float* m_geo  = (const float*)d_in[5];
    const float* v_geo  = (const float*)d_in[6];
    const float* W_feat = (const float*)d_in[7];
    const float* g_feat = (const float*)d_in[8];
    const float* b_feat = (const float*)d_in[9];
    const float* m_feat = (const float*)d_in[10];
    const float* v_feat = (const float*)d_in[11];
    float* out = (float*)d_out;

    constants_kernel<<<1, 256>>>(g_geo, b_geo, m_geo, v_geo,
                                 g_feat, b_feat, m_feat, v_feat);
    geo_precompute_kernel<<<(NB * NPTS * 128) / 256, 256>>>(xyz, W_geo);
    feat_gemm_kernel<<<dim3(NPTS / 32, NB), 128>>>(f, W_feat);
    knn_kernel<<<dim3(NPTS / 8, NB), 256>>>(xyz);
    gather_max_kernel<<<dim3(NPTS / 32, NB), 256>>>(out);
}